// round 6
// baseline (speedup 1.0000x reference)
#include <cuda_runtime.h>
#include <cstdint>

#define BB 16
#define HH 1024
#define WW 1024
#define WORDS 32                    // uint32 words per row
#define HW (HH * WW)
#define NPIX (BB * HW)

#define TROWS 32                            // tile rows per block
#define NTILES ((BB * HH) / TROWS)          // 512 blocks
#define NTHR 256
#define HALO 5
#define SROWS (TROWS + 2 * HALO)            // 42 packed rows in smem

__device__ unsigned long long g_ecount;
__device__ double g_A;
__device__ double g_B;
__device__ unsigned g_done;

__device__ __forceinline__ float ex2f(float x) {
    float r; asm("ex2.approx.f32 %0, %1;" : "=f"(r) : "f"(x)); return r;
}
__device__ __forceinline__ void cpa16(void* dst, const void* src) {
    unsigned d = (unsigned)__cvta_generic_to_shared(dst);
    asm volatile("cp.async.cg.shared.global [%0], [%1], 16;" :: "r"(d), "l"(src));
}
__device__ __forceinline__ void cpa_commit() {
    asm volatile("cp.async.commit_group;" ::: "memory");
}
template <int N>
__device__ __forceinline__ void cpa_wait() {
    asm volatile("cp.async.wait_group %0;" :: "n"(N) : "memory");
}

__global__ void __launch_bounds__(NTHR, 4)
k_tile(const float* __restrict__ s0, const float* __restrict__ s1,
       const int* __restrict__ tgt, float* __restrict__ out) {
    __shared__ unsigned st[SROWS * WORDS];     // packed target bits (tile+halo)
    __shared__ unsigned se[TROWS * WORDS];     // packed edge bits
    __shared__ float sbuf[2][4][WW];           // cp.async stages: 2 x 4 arrays x 1 row
    __shared__ float sA[NTHR];
    __shared__ float sB[NTHR];
    __shared__ unsigned s_cnt;

    const int tid  = threadIdx.x;
    const int lane = tid & 31;
    const int bimg = blockIdx.x >> 5;            // image index
    const int row0 = (blockIdx.x & 31) * TROWS;  // first tile row in image
    const int col4 = tid * 4;                    // this thread's 4-px column
    const int wj   = tid >> 3;                   // word index within row
    const int shb  = (tid & 7) * 4;              // bit shift within word

    // score base pointers for this tile (thread-offset included)
    const size_t pbase = (size_t)bimg * 2 * HW + (size_t)row0 * WW + col4;
    const float* p00 = s0 + pbase;
    const float* p01 = p00 + HW;
    const float* p10 = s1 + pbase;
    const float* p11 = p10 + HW;

    // stage issue: copy one score row (4 arrays x 16B per thread) into sbuf
    auto issue_stage = [&](int s) {
        if (s < TROWS) {
            int bf = s & 1;
            size_t off = (size_t)s * WW;
            cpa16(&sbuf[bf][0][col4], p00 + off);
            cpa16(&sbuf[bf][1][col4], p01 + off);
            cpa16(&sbuf[bf][2][col4], p10 + off);
            cpa16(&sbuf[bf][3][col4], p11 + off);
        }
        cpa_commit();
    };

    // ---- prologue: get score traffic in flight BEFORE the bit phases ------
    issue_stage(0);
    issue_stage(1);

    if (tid == 0) s_cnt = 0;

    // ---------- Phase A: pack target bits (tile + halo), MLP=4 -------------
    {
        const unsigned grpmask = 0xFFu << ((lane >> 3) * 8);
        const int4 zero4 = make_int4(0, 0, 0, 0);
        #pragma unroll
        for (int it = 0; it < 11; ++it) {        // 44 rows (2 pad iterations)
            int4 v[4];
            #pragma unroll
            for (int j = 0; j < 4; ++j) {
                int gr = row0 - HALO + it * 4 + j;
                v[j] = ((unsigned)gr < HH)
                     ? *(const int4*)(tgt + ((size_t)bimg * HH + gr) * WW + col4)
                     : zero4;
            }
            #pragma unroll
            for (int j = 0; j < 4; ++j) {
                int r = it * 4 + j;
                unsigned nib = (v[j].x != 0 ? 1u : 0u) | (v[j].y != 0 ? 2u : 0u) |
                               (v[j].z != 0 ? 4u : 0u) | (v[j].w != 0 ? 8u : 0u);
                unsigned word = __reduce_or_sync(grpmask, nib << shb);
                if ((tid & 7) == 0 && r < SROWS) st[r * WORDS + wj] = word;
            }
        }
    }
    __syncthreads();

    // ---------- Phase B: edge words (bit-parallel 11x11, zero-padded) ------
    {
        unsigned ccnt = 0;
        #pragma unroll
        for (int it = 0; it < (TROWS * WORDS) / NTHR; ++it) {
            int w = it * NTHR + tid;
            int r = w >> 5, j = w & 31;
            unsigned orL = 0, orM = 0, orR = 0;
            unsigned anL = ~0u, anM = ~0u, anR = ~0u;
            #pragma unroll
            for (int d = 0; d < 11; ++d) {
                const unsigned* p = st + (r + d) * WORDS;
                unsigned wm = p[j];
                unsigned wl = (j > 0)  ? p[j - 1] : 0u;
                unsigned wr = (j < 31) ? p[j + 1] : 0u;
                orL |= wl; orM |= wm; orR |= wr;
                anL &= wl; anM &= wm; anR &= wr;
            }
            unsigned nL = ~anL, nM = ~anM, nR = ~anR;
            unsigned any1 = orM, any0 = nM;
            #pragma unroll
            for (int s = 1; s <= 5; s++) {
                any1 |= __funnelshift_r(orM, orR, s);
                any1 |= __funnelshift_l(orL, orM, s);
                any0 |= __funnelshift_r(nM, nR, s);
                any0 |= __funnelshift_l(nL, nM, s);
            }
            unsigned T = st[(r + HALO) * WORDS + j];
            unsigned e = (T & any0) | (~T & any1);
            se[w] = e;
            ccnt += __popc(e);
        }
        ccnt = __reduce_add_sync(0xffffffffu, ccnt);
        if (lane == 0) atomicAdd(&s_cnt, ccnt);
    }
    __syncthreads();

    // ---------- Phase C: smem-staged streaming (no syncs in loop) ----------
    // Each thread consumes exactly the bytes it copied. log2-domain math:
    //   -logp_t/ln2             = sp2(-u) = max(-u,0)+lg2(1+ex2(-|u|))
    //   (0.5*logp_t-logp_o)/ln2 = 0.5*sp2(-u) + u
    float accA = 0.f, accB = 0.f;
    {
        const float LOG2E = 1.4426950408889634f;
        for (int s = 0; s < TROWS; ++s) {
            cpa_wait<1>();                      // stage s ready (this thread)
            int bf = s & 1;
            float4 a0 = *(const float4*)&sbuf[bf][0][col4];
            float4 a1 = *(const float4*)&sbuf[bf][1][col4];
            float4 c0 = *(const float4*)&sbuf[bf][2][col4];
            float4 c1 = *(const float4*)&sbuf[bf][3][col4];

            issue_stage(s + 2);                 // refill this buffer

            unsigned tw = st[(s + HALO) * WORDS + wj] >> shb;
            unsigned ew = se[s * WORDS + wj] >> shb;
            unsigned ntw = ~tw;

            float x0[4] = {a0.x, a0.y, a0.z, a0.w};
            float x1[4] = {a1.x, a1.y, a1.z, a1.w};
            float y0[4] = {c0.x, c0.y, c0.z, c0.w};
            float y1[4] = {c1.x, c1.y, c1.z, c1.w};

            #pragma unroll
            for (int k = 0; k < 4; k++) {
                unsigned sflip = (ntw << (31 - k)) & 0x80000000u;
                int      emask = ((int)(ew << (31 - k))) >> 31;

                float d2 = (x1[k] - x0[k]) * LOG2E;
                float u  = __int_as_float(__float_as_int(d2) ^ sflip);
                float z  = ex2f(-fabsf(u));
                float sp = fmaxf(-u, 0.f) + __log2f(1.f + z);

                float e2 = (y1[k] - y0[k]) * LOG2E;
                float v  = __int_as_float(__float_as_int(e2) ^ sflip);
                float z2 = ex2f(-fabsf(v));
                float sq = fmaxf(-v, 0.f) + __log2f(1.f + z2);

                accA += sp + 0.5f * sq;
                float Bt = (0.5f * sp + u) + 0.5f * (0.5f * sq + v);
                accB += __int_as_float(__float_as_int(Bt) & emask);
            }
        }
    }

    // ---------- Block reduction + global accumulation ----------------------
    sA[tid] = accA;
    sB[tid] = accB;
    __syncthreads();
    #pragma unroll
    for (int s = NTHR / 2; s > 0; s >>= 1) {
        if (tid < s) { sA[tid] += sA[tid + s]; sB[tid] += sB[tid + s]; }
        __syncthreads();
    }

    if (tid == 0) {
        atomicAdd(&g_A, (double)sA[0]);
        atomicAdd(&g_B, (double)sB[0]);
        atomicAdd(&g_ecount, (unsigned long long)s_cnt);
        __threadfence();
        unsigned done = atomicAdd(&g_done, 1u);
        if (done == NTILES - 1) {
            const double LN2 = 0.6931471805599453;
            double N = (double)NPIX;
            double a = (double)g_ecount / N;
            if (a > 0.2) a = 0.2;
            out[0] = (float)((g_A + a * g_B) * LN2 / N);
            // reset all state for the next graph replay
            g_A = 0.0; g_B = 0.0; g_ecount = 0ull;
            __threadfence();
            g_done = 0u;
        }
    }
}

// ---------------------------------------------------------------------------
extern "C" void kernel_launch(void* const* d_in, const int* in_sizes, int n_in,
                              void* d_out, int out_size) {
    int ti = 0;
    for (int i = 1; i < n_in; i++)
        if (in_sizes[i] < in_sizes[ti]) ti = i;
    const float* s0 = nullptr;
    const float* s1 = nullptr;
    for (int i = 0; i < n_in; i++) {
        if (i == ti) continue;
        if (!s0) s0 = (const float*)d_in[i];
        else     s1 = (const float*)d_in[i];
    }
    const int* tgt = (const int*)d_in[ti];

    k_tile<<<NTILES, NTHR>>>(s0, s1, tgt, (float*)d_out);
}

// round 8
// speedup vs baseline: 1.0615x; 1.0615x over previous
#include <cuda_runtime.h>
#include <cstdint>

#define BB 16
#define HH 1024
#define WW 1024
#define WORDS 32                    // uint32 words per row
#define HW (HH * WW)
#define NPIX (BB * HW)
#define NWORDS (BB * HH * WORDS)

#define NBLK 592                    // 148 SMs x 4 blocks, co-resident
#define NTHR 256
#define NTHREADS (NBLK * NTHR)
#define NWARPS (NTHREADS / 32)

#define ITROWS 4                    // rows per work item
#define ITEMS ((BB * HH) / ITROWS)  // 4096 items

__device__ unsigned int g_tbits[NWORDS];   // packed target bits (2 MiB)
__device__ unsigned long long g_ecount;
__device__ double g_A;
__device__ double g_B;
__device__ unsigned g_done;
__device__ unsigned g_c1;
__device__ volatile unsigned g_f1;

__device__ __forceinline__ float ex2f(float x) {
    float r; asm("ex2.approx.f32 %0, %1;" : "=f"(r) : "f"(x)); return r;
}

__global__ void __launch_bounds__(NTHR, 4)
k_fused(const float* __restrict__ s0, const float* __restrict__ s1,
        const int* __restrict__ tgt, float* __restrict__ out) {
    __shared__ unsigned se[ITROWS * WORDS];  // edge bits for current item
    __shared__ float sA[NTHR];
    __shared__ float sB[NTHR];
    __shared__ unsigned s_cnt;

    const int tid   = threadIdx.x;
    const int lane  = tid & 31;
    const int gwarp = (blockIdx.x * NTHR + tid) >> 5;

    if (tid == 0) s_cnt = 0;

    // ---------- Phase 1: pack target bits (grid-strided, balanced) ---------
    for (int w = gwarp; w < NPIX / 128; w += NWARPS) {
        int base = w * 128;
        int t0 = tgt[base + lane];
        int t1 = tgt[base + 32 + lane];
        int t2 = tgt[base + 64 + lane];
        int t3 = tgt[base + 96 + lane];
        unsigned b0 = __ballot_sync(0xffffffffu, t0 != 0);
        unsigned b1 = __ballot_sync(0xffffffffu, t1 != 0);
        unsigned b2 = __ballot_sync(0xffffffffu, t2 != 0);
        unsigned b3 = __ballot_sync(0xffffffffu, t3 != 0);
        if (lane == 0)
            *(uint4*)&g_tbits[w * 4] = make_uint4(b0, b1, b2, b3);
    }

    // ---------- Grid barrier -----------------------------------------------
    __syncthreads();
    if (tid == 0) {
        __threadfence();
        if (atomicAdd(&g_c1, 1u) == NBLK - 1) g_f1 = 1u;
        else while (g_f1 == 0u) __nanosleep(32);
        __threadfence();
    }
    __syncthreads();

    // ---------- Phase 2: items of 4 rows, statically strided ---------------
    float accA = 0.f, accB = 0.f;
    unsigned ecnt = 0;
    const float LOG2E = 1.4426950408889634f;

    const int rsub = tid >> 7;               // phase-C row within pair
    const int c8   = (tid & 127) * 8;        // 8-px column
    const int wj8  = c8 >> 5;
    const int sh8  = c8 & 31;

    for (int it = blockIdx.x; it < ITEMS; it += NBLK) {
        int bimg = it >> 8;                  // item / (HH/ITROWS)
        int r0   = (it & 255) * ITROWS;
        int wbase = (bimg * HH + r0) * WORDS;   // g_tbits word base of row r0

        __syncthreads();                     // protect se from prior readers

        // ---- edge words: 128 threads, one word each (4 rows x 32 words) ---
        if (tid < ITROWS * WORDS) {
            int rl = tid >> 5, j = tid & 31;
            int gr0 = r0 + rl;
            unsigned orL = 0, orM = 0, orR = 0;
            unsigned anL = ~0u, anM = ~0u, anR = ~0u;
            unsigned T = 0;
            #pragma unroll
            for (int d = 0; d < 11; ++d) {
                int gr = gr0 + d - 5;
                unsigned wl = 0, wm = 0, wr = 0;
                if ((unsigned)gr < HH) {
                    const unsigned* p = g_tbits + (bimg * HH + gr) * WORDS;
                    wm = p[j];
                    wl = (j > 0)  ? p[j - 1] : 0u;
                    wr = (j < 31) ? p[j + 1] : 0u;
                }
                if (d == 5) T = wm;
                orL |= wl; orM |= wm; orR |= wr;
                anL &= wl; anM &= wm; anR &= wr;
            }
            unsigned nL = ~anL, nM = ~anM, nR = ~anR;
            unsigned any1 = orM, any0 = nM;
            #pragma unroll
            for (int s = 1; s <= 5; s++) {
                any1 |= __funnelshift_r(orM, orR, s);
                any1 |= __funnelshift_l(orL, orM, s);
                any0 |= __funnelshift_r(nM, nR, s);
                any0 |= __funnelshift_l(nL, nM, s);
            }
            unsigned e = (T & any0) | (~T & any1);
            se[tid] = e;
            ecnt += __popc(e);
        }
        __syncthreads();

        // ---- stream scores: 2 iterations x (2 rows x 8 px/thread) ---------
        size_t pixbase = (size_t)bimg * 2 * HW + (size_t)(r0 + rsub) * WW + c8;
        const float* p00 = s0 + pixbase;
        const float* p01 = p00 + HW;
        const float* p10 = s1 + pixbase;
        const float* p11 = p10 + HW;

        #pragma unroll
        for (int i = 0; i < ITROWS / 2; ++i) {
            size_t off = (size_t)(i * 2) * WW;
            float4 a0  = *(const float4*)(p00 + off);
            float4 a0b = *(const float4*)(p00 + off + 4);
            float4 a1  = *(const float4*)(p01 + off);
            float4 a1b = *(const float4*)(p01 + off + 4);
            float4 c0  = *(const float4*)(p10 + off);
            float4 c0b = *(const float4*)(p10 + off + 4);
            float4 c1  = *(const float4*)(p11 + off);
            float4 c1b = *(const float4*)(p11 + off + 4);

            int rl = i * 2 + rsub;
            unsigned tw = g_tbits[wbase + rl * WORDS + wj8] >> sh8;
            unsigned ew = se[rl * WORDS + wj8] >> sh8;
            unsigned ntw = ~tw;

            float x0[8] = {a0.x, a0.y, a0.z, a0.w, a0b.x, a0b.y, a0b.z, a0b.w};
            float x1[8] = {a1.x, a1.y, a1.z, a1.w, a1b.x, a1b.y, a1b.z, a1b.w};
            float y0[8] = {c0.x, c0.y, c0.z, c0.w, c0b.x, c0b.y, c0b.z, c0b.w};
            float y1[8] = {c1.x, c1.y, c1.z, c1.w, c1b.x, c1b.y, c1b.z, c1b.w};

            #pragma unroll
            for (int k = 0; k < 8; k++) {
                unsigned sflip = (ntw << (31 - k)) & 0x80000000u;
                int      emask = ((int)(ew << (31 - k))) >> 31;

                float d2 = (x1[k] - x0[k]) * LOG2E;
                float u  = __int_as_float(__float_as_int(d2) ^ sflip);
                float z  = ex2f(-fabsf(u));
                float sp = fmaxf(-u, 0.f) + __log2f(1.f + z);

                float e2 = (y1[k] - y0[k]) * LOG2E;
                float v  = __int_as_float(__float_as_int(e2) ^ sflip);
                float z2 = ex2f(-fabsf(v));
                float sq = fmaxf(-v, 0.f) + __log2f(1.f + z2);

                accA += sp + 0.5f * sq;
                float Bt = (0.5f * sp + u) + 0.5f * (0.5f * sq + v);
                accB += __int_as_float(__float_as_int(Bt) & emask);
            }
        }
    }

    // ---------- Block reduction + global accumulation ----------------------
    ecnt = __reduce_add_sync(0xffffffffu, ecnt);
    if (lane == 0 && ecnt) atomicAdd(&s_cnt, ecnt);

    sA[tid] = accA;
    sB[tid] = accB;
    __syncthreads();
    #pragma unroll
    for (int s = NTHR / 2; s > 0; s >>= 1) {
        if (tid < s) { sA[tid] += sA[tid + s]; sB[tid] += sB[tid + s]; }
        __syncthreads();
    }

    if (tid == 0) {
        atomicAdd(&g_A, (double)sA[0]);
        atomicAdd(&g_B, (double)sB[0]);
        atomicAdd(&g_ecount, (unsigned long long)s_cnt);
        __threadfence();
        unsigned done = atomicAdd(&g_done, 1u);
        if (done == NBLK - 1) {
            const double LN2 = 0.6931471805599453;
            double N = (double)NPIX;
            double a = (double)g_ecount / N;
            if (a > 0.2) a = 0.2;
            out[0] = (float)((g_A + a * g_B) * LN2 / N);
            // reset ALL state for the next graph replay
            g_A = 0.0; g_B = 0.0; g_ecount = 0ull;
            g_c1 = 0u; g_f1 = 0u;
            __threadfence();
            g_done = 0u;
        }
    }
}

// ---------------------------------------------------------------------------
extern "C" void kernel_launch(void* const* d_in, const int* in_sizes, int n_in,
                              void* d_out, int out_size) {
    int ti = 0;
    for (int i = 1; i < n_in; i++)
        if (in_sizes[i] < in_sizes[ti]) ti = i;
    const float* s0 = nullptr;
    const float* s1 = nullptr;
    for (int i = 0; i < n_in; i++) {
        if (i == ti) continue;
        if (!s0) s0 = (const float*)d_in[i];
        else     s1 = (const float*)d_in[i];
    }
    const int* tgt = (const int*)d_in[ti];

    k_fused<<<NBLK, NTHR>>>(s0, s1, tgt, (float*)d_out);
}